// round 9
// baseline (speedup 1.0000x reference)
#include <cuda_runtime.h>
#include <cuda_fp16.h>
#include <cstdint>

// NAryTreeLSTMCell — round 9: probe fp16-accumulator HMMA rate.
// Round 8 sits at the legacy tensor wall (rt~16/SMSP for HMMA.16816 f32-acc).
// If sm_103a's fallback path (like consumer Blackwell) runs f16-acc at 2x, this
// kernel halves the mainloop. f16 partials are promoted to fp32 once per
// 128-K chunk (error ~6e-4 pre-activation, within the 1e-3 gate).
// Also merges the two pack kernels into one launch.
// ARITY=2, LABEL_DIM=128, H_DIM=512, B=16384, ARG_DIM=1152.

namespace {
constexpr int Bsz = 16384;
constexpr int H   = 512;
constexpr int L   = 128;
constexpr int K   = 1152;
constexpr int NG  = 5;
constexpr int BM  = 128;           // batch rows / CTA
constexpr int BNR = 320;           // B rows: 5 gates x 64 h
constexpr int BHh = 64;            // h per gate per CTA
constexpr int BK  = 128;           // K per chunk
constexpr int NCHUNK = K / BK;     // 9
constexpr int THREADS = 512;       // 16 warps: 4(m) x 4(n)

constexpr uint32_t AG = BM * 16;    // 2048
constexpr uint32_t BG = BNR * 16;   // 5120
constexpr uint32_t A_TILE = 16 * AG;               // 32768 B
constexpr uint32_t B_TILE = 16 * BG;               // 81920 B
constexpr uint32_t OFF_A = 0;
constexpr uint32_t OFF_B = A_TILE;
constexpr uint32_t STAGE_BYTES = A_TILE + B_TILE;  // 114688
constexpr uint32_t SMEM_TOTAL  = 2 * STAGE_BYTES + 64;

constexpr int NX = Bsz * (K / 4);            // pack work items for X
constexpr int NW = NG * H * (K / 4);         // pack work items for W
} // namespace

// ---- scratch: chunk-tiled, granule-blocked images (exact SMEM layout) ----
__device__ __half g_Xt[(size_t)NCHUNK * (Bsz / BM) * (A_TILE / 2)];
__device__ __half g_Wt[(size_t)NCHUNK * (H / BHh) * (B_TILE / 2)];

// ---- PTX helpers ----
__device__ __forceinline__ uint32_t smem_u32(const void* p) {
    return (uint32_t)__cvta_generic_to_shared(p);
}
__device__ __forceinline__ void bulk_cp(uint32_t dst, const void* src,
                                        uint32_t bytes, uint32_t mbar) {
    asm volatile("cp.async.bulk.shared::cta.global.mbarrier::complete_tx::bytes "
                 "[%0], [%1], %2, [%3];"
                 :: "r"(dst), "l"(src), "r"(bytes), "r"(mbar) : "memory");
}
__device__ __forceinline__ void mbar_init(uint32_t a, uint32_t cnt) {
    asm volatile("mbarrier.init.shared.b64 [%0], %1;" :: "r"(a), "r"(cnt) : "memory");
}
__device__ __forceinline__ void mbar_expect(uint32_t a, uint32_t bytes) {
    asm volatile("mbarrier.arrive.expect_tx.shared::cta.b64 _, [%0], %1;"
                 :: "r"(a), "r"(bytes) : "memory");
}
__device__ __forceinline__ void mbar_wait(uint32_t a, uint32_t ph) {
    asm volatile("{\n.reg .pred P;\nLW%=:\n"
                 "mbarrier.try_wait.parity.shared::cta.b64 P, [%0], %1;\n"
                 "@!P bra LW%=;\n}" :: "r"(a), "r"(ph) : "memory");
}
__device__ __forceinline__ void ldsm4(uint32_t* r, uint32_t a) {
    asm volatile("ldmatrix.sync.aligned.m8n8.x4.shared.b16 {%0,%1,%2,%3}, [%4];"
                 : "=r"(r[0]), "=r"(r[1]), "=r"(r[2]), "=r"(r[3]) : "r"(a));
}
// f16-accumulate mma: D,C are 2x f16x2 regs
__device__ __forceinline__ void mma_f16acc(uint32_t* d, const uint32_t* a,
                                           const uint32_t* b) {
    asm volatile("mma.sync.aligned.m16n8k16.row.col.f16.f16.f16.f16 "
                 "{%0,%1}, {%2,%3,%4,%5}, {%6,%7}, {%0,%1};"
                 : "+r"(d[0]), "+r"(d[1])
                 : "r"(a[0]), "r"(a[1]), "r"(a[2]), "r"(a[3]), "r"(b[0]), "r"(b[1]));
}
__device__ __forceinline__ float sigmf(float x) { return 1.0f / (1.0f + __expf(-x)); }

// ---- merged pack kernel: fp32 -> fp16 tile images for X and W ----
__global__ void pack_all(const float* __restrict__ label, const float* __restrict__ ch_h,
                         const float* __restrict__ Wi, const float* __restrict__ Wo,
                         const float* __restrict__ Wu, const float* __restrict__ Wfl,
                         const float* __restrict__ Wfs) {
    int i = blockIdx.x * blockDim.x + threadIdx.x;
    if (i < NX) {
        int b = i / (K / 4);
        int d = (i % (K / 4)) * 4;
        const float* src;
        if (d < L) src = label + (size_t)b * L + d;
        else {
            int dd = d - L; int j = dd >> 9; int hh = dd & 511;
            src = ch_h + (((size_t)(j * Bsz + b)) << 9) + hh;
        }
        float4 v = *reinterpret_cast<const float4*>(src);
        __half h4[4] = {__float2half_rn(v.x), __float2half_rn(v.y),
                        __float2half_rn(v.z), __float2half_rn(v.w)};
        int c  = d >> 7, kk = d & 127, g = kk >> 3;
        int mt = b >> 7, r = b & 127;
        size_t o = ((size_t)(c * 128 + mt)) * (A_TILE / 2) + (size_t)g * 1024 + r * 8 + (kk & 7);
        *reinterpret_cast<uint2*>(&g_Xt[o]) = *reinterpret_cast<uint2*>(h4);
    } else if (i < NX + NW) {
        int u  = i - NX;
        int rw = u / (K / 4);
        int d  = (u % (K / 4)) * 4;
        int gate = rw >> 9, h = rw & 511;
        const float* src;
        if (gate == 0)      src = Wi + (size_t)h * K + d;
        else if (gate == 1) src = Wo + (size_t)h * K + d;
        else if (gate == 2) src = Wu + (size_t)h * K + d;
        else if (d < L)     src = Wfl + (size_t)h * L + d;
        else {
            int dd = d - L; int j = dd >> 9; int hh = dd & 511;
            src = Wfs + (((size_t)(((gate - 3) * 2 + j) * H + h)) << 9) + hh;
        }
        float4 v = *reinterpret_cast<const float4*>(src);
        __half h4[4] = {__float2half_rn(v.x), __float2half_rn(v.y),
                        __float2half_rn(v.z), __float2half_rn(v.w)};
        int c   = d >> 7, kk = d & 127, g = kk >> 3;
        int bht = h >> 6;
        int rr  = gate * 64 + (h & 63);
        size_t o = ((size_t)(c * 8 + bht)) * (B_TILE / 2) + (size_t)g * 2560 + rr * 8 + (kk & 7);
        *reinterpret_cast<uint2*>(&g_Wt[o]) = *reinterpret_cast<uint2*>(h4);
    }
}

// ---- main kernel ----
__global__ __launch_bounds__(THREADS, 1)
void treelstm_mma(const float* __restrict__ ch_c,
                  const float* __restrict__ b_i, const float* __restrict__ b_o,
                  const float* __restrict__ b_u, const float* __restrict__ fbias,
                  float* __restrict__ out) {
    extern __shared__ char smem[];
    const uint32_t sbase = smem_u32(smem);
    const int tid  = threadIdx.x;
    const int wid  = tid >> 5, lane = tid & 31;
    const int wm   = wid & 3;
    const int wn   = wid >> 2;
    const int bht  = blockIdx.x;
    const int mt   = blockIdx.y;
    const int bh0  = bht * BHh;
    const int bm0  = mt * BM;

    const uint32_t STG0 = sbase;
    const uint32_t STG1 = sbase + STAGE_BYTES;
    const uint32_t mb0  = sbase + 2 * STAGE_BYTES;
    const uint32_t mb1  = mb0 + 16;

    const char* Abase = reinterpret_cast<const char*>(g_Xt);
    const char* Bbase = reinterpret_cast<const char*>(g_Wt);
    auto Asrc = [&](int c) { return Abase + ((size_t)(c * 128 + mt)) * A_TILE; };
    auto Bsrc = [&](int c) { return Bbase + ((size_t)(c * 8 + bht)) * B_TILE; };

    if (tid == 0) { mbar_init(mb0, 1); mbar_init(mb1, 1); }
    __syncthreads();
    if (tid == 0) {
        mbar_expect(mb0, STAGE_BYTES);
        bulk_cp(STG0 + OFF_A, Asrc(0), A_TILE, mb0);
        bulk_cp(STG0 + OFF_B, Bsrc(0), B_TILE, mb0);
        mbar_expect(mb1, STAGE_BYTES);
        bulk_cp(STG1 + OFF_A, Asrc(1), A_TILE, mb1);
        bulk_cp(STG1 + OFF_B, Bsrc(1), B_TILE, mb1);
    }

    const int ar  = ((lane >> 3) & 1) * 8 + (lane & 7);
    const uint32_t aBase = (uint32_t)((wm * 32 + ar) * 16) + (uint32_t)(lane >> 4) * AG;
    const int br  = ((lane >> 4) & 1) * 8 + (lane & 7);
    const uint32_t bBase = (uint32_t)((wn * 80 + br) * 16) + (uint32_t)((lane >> 3) & 1) * BG;

    float acc[2][10][4];
    #pragma unroll
    for (int mi = 0; mi < 2; mi++)
        #pragma unroll
        for (int ni = 0; ni < 10; ni++)
            #pragma unroll
            for (int q = 0; q < 4; q++) acc[mi][ni][q] = 0.0f;

    uint32_t ph0 = 0, ph1 = 0;
    for (int k = 0; k < NCHUNK; k++) {
        const int s = k & 1;
        const uint32_t stg = s ? STG1 : STG0;
        if (s) { mbar_wait(mb1, ph1); ph1 ^= 1; }
        else   { mbar_wait(mb0, ph0); ph0 ^= 1; }

        // np-outer: accumulate this chunk's 8 k16 steps in f16, promote once.
        #pragma unroll
        for (int np = 0; np < 5; np++) {
            uint32_t d[8];                         // f16x2 partials: [mi][n8][2]
            #pragma unroll
            for (int q = 0; q < 8; q++) d[q] = 0u;
            #pragma unroll
            for (int ks = 0; ks < 8; ks++) {
                const uint32_t aAddr = stg + OFF_A + aBase + (uint32_t)(2 * ks) * AG;
                const uint32_t bAddr = stg + OFF_B + bBase + (uint32_t)(2 * ks) * BG
                                       + (uint32_t)np * 256;
                uint32_t a[8];
                ldsm4(a + 0, aAddr);
                ldsm4(a + 4, aAddr + 256);
                uint32_t b[4];
                ldsm4(b, bAddr);
                mma_f16acc(d + 0, a + 0, b + 0);
                mma_f16acc(d + 2, a + 0, b + 2);
                mma_f16acc(d + 4, a + 4, b + 0);
                mma_f16acc(d + 6, a + 4, b + 2);
            }
            // promote f16 partials -> fp32 master accumulators
            #pragma unroll
            for (int mi = 0; mi < 2; mi++)
                #pragma unroll
                for (int n8 = 0; n8 < 2; n8++) {
                    const int ni = np * 2 + n8;
                    const uint32_t* dp = d + mi * 4 + n8 * 2;
                    float2 lo = __half22float2(*reinterpret_cast<const __half2*>(&dp[0]));
                    float2 hi = __half22float2(*reinterpret_cast<const __half2*>(&dp[1]));
                    acc[mi][ni][0] += lo.x;
                    acc[mi][ni][1] += lo.y;
                    acc[mi][ni][2] += hi.x;
                    acc[mi][ni][3] += hi.y;
                }
        }
        __syncthreads();                            // stage s fully consumed
        if (k + 2 < NCHUNK && tid == 0) {
            const uint32_t mb = s ? mb1 : mb0;
            mbar_expect(mb, STAGE_BYTES);
            bulk_cp(stg + OFF_A, Asrc(k + 2), A_TILE, mb);
            bulk_cp(stg + OFF_B, Bsrc(k + 2), B_TILE, mb);
        }
    }

    // ---- epilogue: recombine gates through SMEM (stride 129 words) ----
    __syncthreads();
    float* gbuf = reinterpret_cast<float*>(smem);   // [320][129]
    #pragma unroll
    for (int mi = 0; mi < 2; mi++)
        #pragma unroll
        for (int ni = 0; ni < 10; ni++) {
            const int m = wm * 32 + mi * 16 + (lane >> 2);
            const int n = wn * 80 + ni * 8 + 2 * (lane & 3);
            gbuf[(size_t)n * 129 + m]           = acc[mi][ni][0];
            gbuf[(size_t)(n + 1) * 129 + m]     = acc[mi][ni][1];
            gbuf[(size_t)n * 129 + m + 8]       = acc[mi][ni][2];
            gbuf[(size_t)(n + 1) * 129 + m + 8] = acc[mi][ni][3];
        }
    __syncthreads();

    for (int idx = tid; idx < BM * BHh; idx += THREADS) {
        const int m = idx >> 6, h = idx & 63;
        const int hg = bh0 + h;
        const int b  = bm0 + m;
        const float vi = gbuf[(size_t)(0 * 64 + h) * 129 + m];
        const float vo = gbuf[(size_t)(1 * 64 + h) * 129 + m];
        const float vu = gbuf[(size_t)(2 * 64 + h) * 129 + m];
        const float v0 = gbuf[(size_t)(3 * 64 + h) * 129 + m];
        const float v1 = gbuf[(size_t)(4 * 64 + h) * 129 + m];
        const float ig = sigmf(vi + __ldg(&b_i[hg]));
        const float og = sigmf(vo + __ldg(&b_o[hg]));
        const float ug = tanhf(vu + __ldg(&b_u[hg]));
        const float f0 = sigmf(v0);
        const float f1 = sigmf(v1);
        const float c0 = ch_c[(size_t)b * H + hg];
        const float c1 = ch_c[(size_t)(Bsz + b) * H + hg];
        const float fb = __ldg(&fbias[hg]);
        const float nc = fmaf(ig, ug, fmaf(f0, c0, fmaf(f1, c1, fb * (c0 + c1))));
        const size_t o = (size_t)b * H + hg;
        out[o] = nc;
        out[(size_t)Bsz * H + o] = tanhf(og * nc);
    }
}

extern "C" void kernel_launch(void* const* d_in, const int* in_sizes, int n_in,
                              void* d_out, int out_size) {
    const float* label = (const float*)d_in[0];
    const float* ch_h  = (const float*)d_in[1];
    const float* ch_c  = (const float*)d_in[2];
    const float* W_i   = (const float*)d_in[3];
    const float* b_i   = (const float*)d_in[4];
    const float* W_o   = (const float*)d_in[5];
    const float* b_o   = (const float*)d_in[6];
    const float* W_u   = (const float*)d_in[7];
    const float* b_u   = (const float*)d_in[8];
    const float* W_fl  = (const float*)d_in[9];
    const float* W_fs  = (const float*)d_in[10];
    const float* fb    = (const float*)d_in[11];

    pack_all<<<(NX + NW + 255) / 256, 256>>>(label, ch_h, W_i, W_o, W_u, W_fl, W_fs);

    cudaFuncSetAttribute(treelstm_mma, cudaFuncAttributeMaxDynamicSharedMemorySize, SMEM_TOTAL);
    dim3 grid(H / BHh, Bsz / BM);   // (8, 128)
    treelstm_mma<<<grid, THREADS, SMEM_TOTAL>>>(ch_c, b_i, b_o, b_u, fb, (float*)d_out);
}

// round 10
// speedup vs baseline: 1.2358x; 1.2358x over previous
#include <cuda_runtime.h>
#include <cuda_fp16.h>
#include <cstdint>

// NAryTreeLSTMCell — round 10: round-8 math (fp16 mma, fp32 acc) + one-deep
// software pipelining of ldmatrix fragments (hide LDS->MMA RAW latency, which
// the round-9 profile exposed: tensor pipe only ~55% busy, occ RF-capped at 16
// warps/SM so HW can't hide it alone).
// ARITY=2, LABEL_DIM=128, H_DIM=512, B=16384, ARG_DIM=1152.

namespace {
constexpr int Bsz = 16384;
constexpr int H   = 512;
constexpr int L   = 128;
constexpr int K   = 1152;
constexpr int NG  = 5;
constexpr int BM  = 128;           // batch rows / CTA
constexpr int BNR = 320;           // B rows: 5 gates x 64 h
constexpr int BHh = 64;            // h per gate per CTA
constexpr int BK  = 128;           // K per chunk
constexpr int NCHUNK = K / BK;     // 9
constexpr int THREADS = 512;       // 16 warps: 4(m) x 4(n)

constexpr uint32_t AG = BM * 16;    // 2048
constexpr uint32_t BG = BNR * 16;   // 5120
constexpr uint32_t A_TILE = 16 * AG;               // 32768 B
constexpr uint32_t B_TILE = 16 * BG;               // 81920 B
constexpr uint32_t OFF_A = 0;
constexpr uint32_t OFF_B = A_TILE;
constexpr uint32_t STAGE_BYTES = A_TILE + B_TILE;  // 114688
constexpr uint32_t SMEM_TOTAL  = 2 * STAGE_BYTES + 64;

constexpr int NX = Bsz * (K / 4);
constexpr int NW = NG * H * (K / 4);
} // namespace

// ---- scratch: chunk-tiled, granule-blocked images (exact SMEM layout) ----
__device__ __half g_Xt[(size_t)NCHUNK * (Bsz / BM) * (A_TILE / 2)];
__device__ __half g_Wt[(size_t)NCHUNK * (H / BHh) * (B_TILE / 2)];

// ---- PTX helpers ----
__device__ __forceinline__ uint32_t smem_u32(const void* p) {
    return (uint32_t)__cvta_generic_to_shared(p);
}
__device__ __forceinline__ void bulk_cp(uint32_t dst, const void* src,
                                        uint32_t bytes, uint32_t mbar) {
    asm volatile("cp.async.bulk.shared::cta.global.mbarrier::complete_tx::bytes "
                 "[%0], [%1], %2, [%3];"
                 :: "r"(dst), "l"(src), "r"(bytes), "r"(mbar) : "memory");
}
__device__ __forceinline__ void mbar_init(uint32_t a, uint32_t cnt) {
    asm volatile("mbarrier.init.shared.b64 [%0], %1;" :: "r"(a), "r"(cnt) : "memory");
}
__device__ __forceinline__ void mbar_expect(uint32_t a, uint32_t bytes) {
    asm volatile("mbarrier.arrive.expect_tx.shared::cta.b64 _, [%0], %1;"
                 :: "r"(a), "r"(bytes) : "memory");
}
__device__ __forceinline__ void mbar_wait(uint32_t a, uint32_t ph) {
    asm volatile("{\n.reg .pred P;\nLW%=:\n"
                 "mbarrier.try_wait.parity.shared::cta.b64 P, [%0], %1;\n"
                 "@!P bra LW%=;\n}" :: "r"(a), "r"(ph) : "memory");
}
__device__ __forceinline__ void ldsm4(uint32_t* r, uint32_t a) {
    asm volatile("ldmatrix.sync.aligned.m8n8.x4.shared.b16 {%0,%1,%2,%3}, [%4];"
                 : "=r"(r[0]), "=r"(r[1]), "=r"(r[2]), "=r"(r[3]) : "r"(a));
}
__device__ __forceinline__ void mma_f16(float* c, const uint32_t* a, const uint32_t* b) {
    asm volatile("mma.sync.aligned.m16n8k16.row.col.f32.f16.f16.f32 "
                 "{%0,%1,%2,%3}, {%4,%5,%6,%7}, {%8,%9}, {%0,%1,%2,%3};"
                 : "+f"(c[0]), "+f"(c[1]), "+f"(c[2]), "+f"(c[3])
                 : "r"(a[0]), "r"(a[1]), "r"(a[2]), "r"(a[3]), "r"(b[0]), "r"(b[1]));
}
__device__ __forceinline__ float sigmf(float x) { return 1.0f / (1.0f + __expf(-x)); }

// ---- merged pack kernel: fp32 -> fp16 tile images for X and W ----
__global__ void pack_all(const float* __restrict__ label, const float* __restrict__ ch_h,
                         const float* __restrict__ Wi, const float* __restrict__ Wo,
                         const float* __restrict__ Wu, const float* __restrict__ Wfl,
                         const float* __restrict__ Wfs) {
    int i = blockIdx.x * blockDim.x + threadIdx.x;
    if (i < NX) {
        int b = i / (K / 4);
        int d = (i % (K / 4)) * 4;
        const float* src;
        if (d < L) src = label + (size_t)b * L + d;
        else {
            int dd = d - L; int j = dd >> 9; int hh = dd & 511;
            src = ch_h + (((size_t)(j * Bsz + b)) << 9) + hh;
        }
        float4 v = *reinterpret_cast<const float4*>(src);
        __half h4[4] = {__float2half_rn(v.x), __float2half_rn(v.y),
                        __float2half_rn(v.z), __float2half_rn(v.w)};
        int c  = d >> 7, kk = d & 127, g = kk >> 3;
        int mt = b >> 7, r = b & 127;
        size_t o = ((size_t)(c * 128 + mt)) * (A_TILE / 2) + (size_t)g * 1024 + r * 8 + (kk & 7);
        *reinterpret_cast<uint2*>(&g_Xt[o]) = *reinterpret_cast<uint2*>(h4);
    } else if (i < NX + NW) {
        int u  = i - NX;
        int rw = u / (K / 4);
        int d  = (u % (K / 4)) * 4;
        int gate = rw >> 9, h = rw & 511;
        const float* src;
        if (gate == 0)      src = Wi + (size_t)h * K + d;
        else if (gate == 1) src = Wo + (size_t)h * K + d;
        else if (gate == 2) src = Wu + (size_t)h * K + d;
        else if (d < L)     src = Wfl + (size_t)h * L + d;
        else {
            int dd = d - L; int j = dd >> 9; int hh = dd & 511;
            src = Wfs + (((size_t)(((gate - 3) * 2 + j) * H + h)) << 9) + hh;
        }
        float4 v = *reinterpret_cast<const float4*>(src);
        __half h4[4] = {__float2half_rn(v.x), __float2half_rn(v.y),
                        __float2half_rn(v.z), __float2half_rn(v.w)};
        int c   = d >> 7, kk = d & 127, g = kk >> 3;
        int bht = h >> 6;
        int rr  = gate * 64 + (h & 63);
        size_t o = ((size_t)(c * 8 + bht)) * (B_TILE / 2) + (size_t)g * 2560 + rr * 8 + (kk & 7);
        *reinterpret_cast<uint2*>(&g_Wt[o]) = *reinterpret_cast<uint2*>(h4);
    }
}

// ---- main kernel ----
__global__ __launch_bounds__(THREADS, 1)
void treelstm_mma(const float* __restrict__ ch_c,
                  const float* __restrict__ b_i, const float* __restrict__ b_o,
                  const float* __restrict__ b_u, const float* __restrict__ fbias,
                  float* __restrict__ out) {
    extern __shared__ char smem[];
    const uint32_t sbase = smem_u32(smem);
    const int tid  = threadIdx.x;
    const int wid  = tid >> 5, lane = tid & 31;
    const int wm   = wid & 3;
    const int wn   = wid >> 2;
    const int bht  = blockIdx.x;
    const int mt   = blockIdx.y;
    const int bh0  = bht * BHh;
    const int bm0  = mt * BM;

    const uint32_t STG0 = sbase;
    const uint32_t STG1 = sbase + STAGE_BYTES;
    const uint32_t mb0  = sbase + 2 * STAGE_BYTES;
    const uint32_t mb1  = mb0 + 16;

    const char* Abase = reinterpret_cast<const char*>(g_Xt);
    const char* Bbase = reinterpret_cast<const char*>(g_Wt);
    auto Asrc = [&](int c) { return Abase + ((size_t)(c * 128 + mt)) * A_TILE; };
    auto Bsrc = [&](int c) { return Bbase + ((size_t)(c * 8 + bht)) * B_TILE; };

    if (tid == 0) { mbar_init(mb0, 1); mbar_init(mb1, 1); }
    __syncthreads();
    if (tid == 0) {
        mbar_expect(mb0, STAGE_BYTES);
        bulk_cp(STG0 + OFF_A, Asrc(0), A_TILE, mb0);
        bulk_cp(STG0 + OFF_B, Bsrc(0), B_TILE, mb0);
        mbar_expect(mb1, STAGE_BYTES);
        bulk_cp(STG1 + OFF_A, Asrc(1), A_TILE, mb1);
        bulk_cp(STG1 + OFF_B, Bsrc(1), B_TILE, mb1);
    }

    const int ar  = ((lane >> 3) & 1) * 8 + (lane & 7);
    const uint32_t aBase = (uint32_t)((wm * 32 + ar) * 16) + (uint32_t)(lane >> 4) * AG;
    const int br  = ((lane >> 4) & 1) * 8 + (lane & 7);
    const uint32_t bBase = (uint32_t)((wn * 80 + br) * 16) + (uint32_t)((lane >> 3) & 1) * BG;

    float acc[2][10][4];
    #pragma unroll
    for (int mi = 0; mi < 2; mi++)
        #pragma unroll
        for (int ni = 0; ni < 10; ni++)
            #pragma unroll
            for (int q = 0; q < 4; q++) acc[mi][ni][q] = 0.0f;

    uint32_t ph0 = 0, ph1 = 0;
    for (int k = 0; k < NCHUNK; k++) {
        const int s = k & 1;
        const uint32_t stg = s ? STG1 : STG0;
        if (s) { mbar_wait(mb1, ph1); ph1 ^= 1; }
        else   { mbar_wait(mb0, ph0); ph0 ^= 1; }

        // flattened (ks, np) loop: 40 iterations, one-deep operand pipelining.
        // B fragment for it+1 (and A pair at ks boundaries) is loaded BEFORE the
        // MMAs of it, so every mma reads fragments fetched >=1 iteration ago.
        uint32_t A[2][8], Bf[2][4];
        ldsm4(A[0] + 0, stg + OFF_A + aBase);
        ldsm4(A[0] + 4, stg + OFF_A + aBase + 256);
        ldsm4(Bf[0],    stg + OFF_B + bBase);
        #pragma unroll
        for (int it = 0; it < 40; it++) {
            const int ks = it / 5, np = it % 5;
            const int cb = it & 1;
            const int ca = ks & 1;
            if (it + 1 < 40) {
                const int ks2 = (it + 1) / 5, np2 = (it + 1) % 5;
                ldsm4(Bf[1 - cb], stg + OFF_B + bBase
                                  + (uint32_t)(2 * ks2) * BG + (uint32_t)np2 * 256);
                if (np2 == 0) {
                    const uint32_t aA = stg + OFF_A + aBase + (uint32_t)(2 * ks2) * AG;
                    ldsm4(A[1 - ca] + 0, aA);
                    ldsm4(A[1 - ca] + 4, aA + 256);
                }
            }
            mma_f16(acc[0][np*2+0], A[ca] + 0, Bf[cb] + 0);
            mma_f16(acc[0][np*2+1], A[ca] + 0, Bf[cb] + 2);
            mma_f16(acc[1][np*2+0], A[ca] + 4, Bf[cb] + 0);
            mma_f16(acc[1][np*2+1], A[ca] + 4, Bf[cb] + 2);
        }
        __syncthreads();                            // stage s fully consumed
        if (k + 2 < NCHUNK && tid == 0) {
            const uint32_t mb = s ? mb1 : mb0;
            mbar_expect(mb, STAGE_BYTES);
            bulk_cp(stg + OFF_A, Asrc(k + 2), A_TILE, mb);
            bulk_cp(stg + OFF_B, Bsrc(k + 2), B_TILE, mb);
        }
    }

    // ---- epilogue: recombine gates through SMEM (stride 129 words) ----
    __syncthreads();
    float* gbuf = reinterpret_cast<float*>(smem);   // [320][129]
    #pragma unroll
    for (int mi = 0; mi < 2; mi++)
        #pragma unroll
        for (int ni = 0; ni < 10; ni++) {
            const int m = wm * 32 + mi * 16 + (lane >> 2);
            const int n = wn * 80 + ni * 8 + 2 * (lane & 3);
            gbuf[(size_t)n * 129 + m]           = acc[mi][ni][0];
            gbuf[(size_t)(n + 1) * 129 + m]     = acc[mi][ni][1];
            gbuf[(size_t)n * 129 + m + 8]       = acc[mi][ni][2];
            gbuf[(size_t)(n + 1) * 129 + m + 8] = acc[mi][ni][3];
        }
    __syncthreads();

    for (int idx = tid; idx < BM * BHh; idx += THREADS) {
        const int m = idx >> 6, h = idx & 63;
        const int hg = bh0 + h;
        const int b  = bm0 + m;
        const float vi = gbuf[(size_t)(0 * 64 + h) * 129 + m];
        const float vo = gbuf[(size_t)(1 * 64 + h) * 129 + m];
        const float vu = gbuf[(size_t)(2 * 64 + h) * 129 + m];
        const float v0 = gbuf[(size_t)(3 * 64 + h) * 129 + m];
        const float v1 = gbuf[(size_t)(4 * 64 + h) * 129 + m];
        const float ig = sigmf(vi + __ldg(&b_i[hg]));
        const float og = sigmf(vo + __ldg(&b_o[hg]));
        const float ug = tanhf(vu + __ldg(&b_u[hg]));
        const float f0 = sigmf(v0);
        const float f1 = sigmf(v1);
        const float c0 = ch_c[(size_t)b * H + hg];
        const float c1 = ch_c[(size_t)(Bsz + b) * H + hg];
        const float fb = __ldg(&fbias[hg]);
        const float nc = fmaf(ig, ug, fmaf(f0, c0, fmaf(f1, c1, fb * (c0 + c1))));
        const size_t o = (size_t)b * H + hg;
        out[o] = nc;
        out[(size_t)Bsz * H + o] = tanhf(og * nc);
    }
}

extern "C" void kernel_launch(void* const* d_in, const int* in_sizes, int n_in,
                              void* d_out, int out_size) {
    const float* label = (const float*)d_in[0];
    const float* ch_h  = (const float*)d_in[1];
    const float* ch_c  = (const float*)d_in[2];
    const float* W_i   = (const float*)d_in[3];
    const float* b_i   = (const float*)d_in[4];
    const float* W_o   = (const float*)d_in[5];
    const float* b_o   = (const float*)d_in[6];
    const float* W_u   = (const float*)d_in[7];
    const float* b_u   = (const float*)d_in[8];
    const float* W_fl  = (const float*)d_in[9];
    const float* W_fs  = (const float*)d_in[10];
    const float* fb    = (const float*)d_in[11];

    pack_all<<<(NX + NW + 255) / 256, 256>>>(label, ch_h, W_i, W_o, W_u, W_fl, W_fs);

    cudaFuncSetAttribute(treelstm_mma, cudaFuncAttributeMaxDynamicSharedMemorySize, SMEM_TOTAL);
    dim3 grid(H / BHh, Bsz / BM);   // (8, 128)
    treelstm_mma<<<grid, THREADS, SMEM_TOTAL>>>(ch_c, b_i, b_o, b_u, fb, (float*)d_out);
}